// round 2
// baseline (speedup 1.0000x reference)
#include <cuda_runtime.h>
#include <cuda_bf16.h>

// ---------------- scratch (device globals; no allocations allowed) ----------
__device__ float g_qkv[8 * 1024 * 4096];      // Q,K channel-major [n][o<1024][s]  (128 MB)
__device__ float g_v[8 * 8 * 4096 * 64];      // V  [n][h][s][d]                  (64 MB)
__device__ float g_y[8 * 512 * 4096];         // attention out, channel-major     (64 MB)
__device__ float2 g_part[512];                // per-block partial (sum, sumsq)
__device__ float g_ada[8 * 1024];             // scales_shifts
__device__ float g_a[8 * 512];                // (scale+1)*rstd
__device__ float g_b[8 * 512];                // shift - mean*a
__device__ float g_bias1[8 * 1536];           // folded qkv bias

#define SAMPLE_ELEMS 2097152                   // 512*64*64
#define ATTN_SMEM ((4096 + 4096 + 64*68 + 64*68) * 4)

// ---------------- stats: per-sample sum / sumsq ------------------------------
__global__ void k_stats(const float* __restrict__ x) {
    int n = blockIdx.x >> 6;
    int ch = blockIdx.x & 63;
    const float* p = x + (size_t)n * SAMPLE_ELEMS + (size_t)ch * 32768;
    float s = 0.f, q = 0.f;
    int t = threadIdx.x;
#pragma unroll
    for (int i = 0; i < 32; i++) {
        float4 v = *(const float4*)(p + (size_t)(i * 256 + t) * 4);
        s += v.x + v.y + v.z + v.w;
        q += v.x * v.x + v.y * v.y + v.z * v.z + v.w * v.w;
    }
#pragma unroll
    for (int off = 16; off; off >>= 1) {
        s += __shfl_down_sync(0xffffffffu, s, off);
        q += __shfl_down_sync(0xffffffffu, q, off);
    }
    __shared__ float ss[8], qq[8];
    int warp = t >> 5, lane = t & 31;
    if (lane == 0) { ss[warp] = s; qq[warp] = q; }
    __syncthreads();
    if (t == 0) {
        float S = 0.f, Q = 0.f;
#pragma unroll
        for (int i = 0; i < 8; i++) { S += ss[i]; Q += qq[i]; }
        g_part[blockIdx.x] = make_float2(S, Q);
    }
}

// ---------------- adaLN: scales_shifts = cond @ W_ada + b_ada ---------------
__global__ void k_ada(const float* __restrict__ cond, const float* __restrict__ Wa,
                      const float* __restrict__ ba) {
    int n = blockIdx.x;
    __shared__ float cs[512];
    int t = threadIdx.x;
    cs[t] = cond[n * 512 + t];
    cs[t + 256] = cond[n * 512 + t + 256];
    __syncthreads();
    float acc[4] = {0.f, 0.f, 0.f, 0.f};
    for (int f = 0; f < 512; f++) {
        float cv = cs[f];
#pragma unroll
        for (int j = 0; j < 4; j++) acc[j] += cv * Wa[f * 1024 + t + j * 256];
    }
#pragma unroll
    for (int j = 0; j < 4; j++) g_ada[n * 1024 + t + j * 256] = acc[j] + ba[t + j * 256];
}

// ---------------- fold LN stats + adaLN into per-channel affine -------------
__global__ void k_ab() {
    int n = blockIdx.x;
    int t = threadIdx.x;  // 512 threads
    __shared__ float s_mean, s_rstd;
    if (t == 0) {
        float S = 0.f, Q = 0.f;
        for (int i = 0; i < 64; i++) {
            float2 p = g_part[n * 64 + i];
            S += p.x; Q += p.y;
        }
        float mean = S / (float)SAMPLE_ELEMS;
        float var = Q / (float)SAMPLE_ELEMS - mean * mean;
        s_mean = mean;
        s_rstd = rsqrtf(var + 1e-5f);
    }
    __syncthreads();
    float scale = g_ada[n * 1024 + t];
    float shift = g_ada[n * 1024 + 512 + t];
    float a = (scale + 1.f) * s_rstd;
    g_a[n * 512 + t] = a;
    g_b[n * 512 + t] = shift - s_mean * a;
}

// ---------------- folded bias: bias1[n,o] = b_qkv[o] + sum_c W[o,c]*b[n,c] --
__global__ void k_bias1(const float* __restrict__ Wqkv, const float* __restrict__ bqkv) {
    int warp = (blockIdx.x * blockDim.x + threadIdx.x) >> 5;
    int lane = threadIdx.x & 31;
    int n = warp / 1536, o = warp % 1536;
    const float* wr = Wqkv + (size_t)o * 512;
    const float* bb = g_b + n * 512;
    float acc = 0.f;
    for (int c = lane; c < 512; c += 32) acc += wr[c] * bb[c];
#pragma unroll
    for (int off = 16; off; off >>= 1) acc += __shfl_xor_sync(0xffffffffu, acc, off);
    if (lane == 0) g_bias1[warp] = bqkv[o] + acc;
}

// ---------------- QKV GEMM (norm folded into A), writes Q/K + V-transposed --
__global__ __launch_bounds__(256) void k_qkv(const float* __restrict__ x,
                                             const float* __restrict__ W) {
    __shared__ float As[16][68];
    __shared__ float Bs[16][68];
    __shared__ float Os[64 * 65];
    int n = blockIdx.z, o0 = blockIdx.y * 64, s0 = blockIdx.x * 64;
    int tid = threadIdx.x, tx = tid & 15, ty = tid >> 4;
    const float* Wp = W + (size_t)o0 * 512;
    const float* xp = x + (size_t)n * 512 * 4096 + s0;
    const float* ap = g_a + n * 512;
    int la_o = tid >> 2, la_k = (tid & 3) * 4;
    int lb_k = tid >> 4, lb_s = (tid & 15) * 4;
    float acc[4][4] = {};
    for (int c0 = 0; c0 < 512; c0 += 16) {
        float4 wv = *(const float4*)(Wp + (size_t)la_o * 512 + c0 + la_k);
        float4 av = *(const float4*)(ap + c0 + la_k);
        As[la_k + 0][la_o] = wv.x * av.x;
        As[la_k + 1][la_o] = wv.y * av.y;
        As[la_k + 2][la_o] = wv.z * av.z;
        As[la_k + 3][la_o] = wv.w * av.w;
        float4 xv = *(const float4*)(xp + (size_t)(c0 + lb_k) * 4096 + lb_s);
        *(float4*)&Bs[lb_k][lb_s] = xv;
        __syncthreads();
#pragma unroll
        for (int kk = 0; kk < 16; kk++) {
            float4 a4 = *(const float4*)&As[kk][ty * 4];
            float4 b4 = *(const float4*)&Bs[kk][tx * 4];
            float ar[4] = {a4.x, a4.y, a4.z, a4.w};
            float br[4] = {b4.x, b4.y, b4.z, b4.w};
#pragma unroll
            for (int i = 0; i < 4; i++)
#pragma unroll
                for (int j = 0; j < 4; j++) acc[i][j] += ar[i] * br[j];
        }
        __syncthreads();
    }
    float bias[4];
#pragma unroll
    for (int i = 0; i < 4; i++) bias[i] = g_bias1[n * 1536 + o0 + ty * 4 + i];

    if (o0 < 1024) {  // Q and K: channel-major [n][o][s]
        float* outp = g_qkv + ((size_t)n * 1024 + o0) * 4096 + s0;
#pragma unroll
        for (int i = 0; i < 4; i++) {
            float4 v = make_float4(acc[i][0] + bias[i], acc[i][1] + bias[i],
                                   acc[i][2] + bias[i], acc[i][3] + bias[i]);
            *(float4*)(outp + (size_t)(ty * 4 + i) * 4096 + tx * 4) = v;
        }
    } else {          // V: transpose to [n][h][s][d]
        int h = (o0 - 1024) >> 6;
#pragma unroll
        for (int i = 0; i < 4; i++)
#pragma unroll
            for (int j = 0; j < 4; j++)
                Os[(tx * 4 + j) * 65 + ty * 4 + i] = acc[i][j] + bias[i];
        __syncthreads();
        float* vout = g_v + ((size_t)(n * 8 + h) * 4096 + s0) * 64;
        int sl = tid >> 2, d4 = (tid & 3) * 16;
#pragma unroll
        for (int u = 0; u < 4; u++) {
            int d = d4 + u * 4;
            float4 v = make_float4(Os[sl * 65 + d], Os[sl * 65 + d + 1],
                                   Os[sl * 65 + d + 2], Os[sl * 65 + d + 3]);
            *(float4*)(vout + (size_t)sl * 64 + d) = v;
        }
    }
}

// ---------------- flash attention: one (n, h, 64-query tile) per block ------
__global__ __launch_bounds__(256) void k_attn() {
    extern __shared__ float sm[];
    float* Qs = sm;                       // [64][64]
    float* Ks = sm + 4096;                // [64][64]
    float* Vt = sm + 8192;                // [64][68]  (rows=ti, cols=d)
    float* Ps = sm + 8192 + 64 * 68;      // [64][68]

    int qt = blockIdx.x, h = blockIdx.y, n = blockIdx.z;
    int tid = threadIdx.x, tx = tid & 15, ty = tid >> 4;
    const float* qb = g_qkv + ((size_t)(n * 1024) + h * 64) * 4096 + qt * 64;
    const float* kb = g_qkv + ((size_t)(n * 1024) + 512 + h * 64) * 4096;
    const float* vb = g_v + (size_t)(n * 8 + h) * 4096 * 64;

    {   // load Q tile, pre-scaled by 1/8 (dh^-0.25 applied to q AND k)
        int ld = tid >> 4, ls = (tid & 15) * 4;
#pragma unroll
        for (int i = 0; i < 4; i++) {
            int d = ld + i * 16;
            float4 v = *(const float4*)(qb + (size_t)d * 4096 + ls);
            v.x *= 0.125f; v.y *= 0.125f; v.z *= 0.125f; v.w *= 0.125f;
            *(float4*)(Qs + d * 64 + ls) = v;
        }
    }
    float acc[4][4] = {};
    float m_run[4], l_run[4];
#pragma unroll
    for (int r = 0; r < 4; r++) { m_run[r] = -1e30f; l_run[r] = 0.f; }

    for (int jt = 0; jt < 64; jt++) {
        {   // load K tile [d][ti] and V tile [ti][d]
            int ld = tid >> 4, ls = (tid & 15) * 4;
#pragma unroll
            for (int i = 0; i < 4; i++) {
                int d = ld + i * 16;
                float4 kv = *(const float4*)(kb + (size_t)d * 4096 + jt * 64 + ls);
                *(float4*)(Ks + d * 64 + ls) = kv;
                int t2 = ld + i * 16;
                float4 vv = *(const float4*)(vb + (size_t)(jt * 64 + t2) * 64 + ls);
                *(float4*)(Vt + t2 * 68 + ls) = vv;
            }
        }
        __syncthreads();

        // S = Q^T K  (thread tile 4 si x 4 ti)
        float s[4][4] = {};
#pragma unroll 8
        for (int d = 0; d < 64; d++) {
            float4 qv = *(const float4*)(Qs + d * 64 + ty * 4);
            float4 kv = *(const float4*)(Ks + d * 64 + tx * 4);
            float qr[4] = {qv.x, qv.y, qv.z, qv.w};
            float kr[4] = {kv.x, kv.y, kv.z, kv.w};
#pragma unroll
            for (int r = 0; r < 4; r++)
#pragma unroll
                for (int c = 0; c < 4; c++) s[r][c] += qr[r] * kr[c];
        }

        // online softmax over this tile
        float p[4][4];
#pragma unroll
        for (int r = 0; r < 4; r++) {
            float mx = fmaxf(fmaxf(s[r][0], s[r][1]), fmaxf(s[r][2], s[r][3]));
            mx = fmaxf(mx, __shfl_xor_sync(0xffffffffu, mx, 1, 16));
            mx = fmaxf(mx, __shfl_xor_sync(0xffffffffu, mx, 2, 16));
            mx = fmaxf(mx, __shfl_xor_sync(0xffffffffu, mx, 4, 16));
            mx = fmaxf(mx, __shfl_xor_sync(0xffffffffu, mx, 8, 16));
            float nm = fmaxf(m_run[r], mx);
            float corr = __expf(m_run[r] - nm);
            float rs = 0.f;
#pragma unroll
            for (int c = 0; c < 4; c++) { p[r][c] = __expf(s[r][c] - nm); rs += p[r][c]; }
            rs += __shfl_xor_sync(0xffffffffu, rs, 1, 16);
            rs += __shfl_xor_sync(0xffffffffu, rs, 2, 16);
            rs += __shfl_xor_sync(0xffffffffu, rs, 4, 16);
            rs += __shfl_xor_sync(0xffffffffu, rs, 8, 16);
            l_run[r] = l_run[r] * corr + rs;
            m_run[r] = nm;
#pragma unroll
            for (int c = 0; c < 4; c++) acc[r][c] *= corr;
        }
#pragma unroll
        for (int r = 0; r < 4; r++)
            *(float4*)(Ps + (ty * 4 + r) * 68 + tx * 4) =
                make_float4(p[r][0], p[r][1], p[r][2], p[r][3]);
        __syncthreads();

        // acc[si][d] += sum_ti Ps[si][ti] * Vt[ti][d]
#pragma unroll 8
        for (int ti = 0; ti < 64; ti++) {
            float pr[4];
#pragma unroll
            for (int r = 0; r < 4; r++) pr[r] = Ps[(ty * 4 + r) * 68 + ti];
            float4 vv = *(const float4*)(Vt + ti * 68 + tx * 4);
            float vr[4] = {vv.x, vv.y, vv.z, vv.w};
#pragma unroll
            for (int r = 0; r < 4; r++)
#pragma unroll
                for (int c = 0; c < 4; c++) acc[r][c] += pr[r] * vr[c];
        }
        __syncthreads();
    }

    // normalize, stage transpose, write y channel-major [n][h*64+d][s]
    float inv_l[4];
#pragma unroll
    for (int r = 0; r < 4; r++) inv_l[r] = 1.f / l_run[r];
    float* Os = Ps;  // reuse, stride 65 (4160 <= 4352 floats)
#pragma unroll
    for (int r = 0; r < 4; r++)
#pragma unroll
        for (int c = 0; c < 4; c++)
            Os[(tx * 4 + c) * 65 + ty * 4 + r] = acc[r][c] * inv_l[r];
    __syncthreads();
    float* yb = g_y + ((size_t)(n * 512) + h * 64) * 4096 + qt * 64;
    int d = tid >> 2, s4 = (tid & 3) * 16;
#pragma unroll
    for (int u = 0; u < 4; u++) {
        int si = s4 + u * 4;
        float4 o = make_float4(Os[d * 65 + si], Os[d * 65 + si + 1],
                               Os[d * 65 + si + 2], Os[d * 65 + si + 3]);
        *(float4*)(yb + (size_t)d * 4096 + si) = o;
    }
}

// ---------------- output projection + bias + residual -----------------------
__global__ __launch_bounds__(256) void k_out(const float* __restrict__ W,
                                             const float* __restrict__ bo,
                                             const float* __restrict__ x,
                                             float* __restrict__ out) {
    __shared__ float As[16][68];
    __shared__ float Bs[16][68];
    int n = blockIdx.z, o0 = blockIdx.y * 64, s0 = blockIdx.x * 64;
    int tid = threadIdx.x, tx = tid & 15, ty = tid >> 4;
    const float* Wp = W + (size_t)o0 * 512;
    const float* yp = g_y + (size_t)n * 512 * 4096 + s0;
    int la_o = tid >> 2, la_k = (tid & 3) * 4;
    int lb_k = tid >> 4, lb_s = (tid & 15) * 4;
    float acc[4][4] = {};
    for (int c0 = 0; c0 < 512; c0 += 16) {
        float4 wv = *(const float4*)(Wp + (size_t)la_o * 512 + c0 + la_k);
        As[la_k + 0][la_o] = wv.x;
        As[la_k + 1][la_o] = wv.y;
        As[la_k + 2][la_o] = wv.z;
        As[la_k + 3][la_o] = wv.w;
        float4 yv = *(const float4*)(yp + (size_t)(c0 + lb_k) * 4096 + lb_s);
        *(float4*)&Bs[lb_k][lb_s] = yv;
        __syncthreads();
#pragma unroll
        for (int kk = 0; kk < 16; kk++) {
            float4 a4 = *(const float4*)&As[kk][ty * 4];
            float4 b4 = *(const float4*)&Bs[kk][tx * 4];
            float ar[4] = {a4.x, a4.y, a4.z, a4.w};
            float br[4] = {b4.x, b4.y, b4.z, b4.w};
#pragma unroll
            for (int i = 0; i < 4; i++)
#pragma unroll
                for (int j = 0; j < 4; j++) acc[i][j] += ar[i] * br[j];
        }
        __syncthreads();
    }
#pragma unroll
    for (int i = 0; i < 4; i++) {
        int o = o0 + ty * 4 + i;
        float bb = bo[o];
        size_t addr = ((size_t)n * 512 + o) * 4096 + s0 + tx * 4;
        float4 xr = *(const float4*)(x + addr);
        float4 v = make_float4(acc[i][0] + bb + xr.x, acc[i][1] + bb + xr.y,
                               acc[i][2] + bb + xr.z, acc[i][3] + bb + xr.w);
        *(float4*)(out + addr) = v;
    }
}

// ---------------- launch -----------------------------------------------------
extern "C" void kernel_launch(void* const* d_in, const int* in_sizes, int n_in,
                              void* d_out, int out_size) {
    const float* x     = (const float*)d_in[0];
    const float* cond  = (const float*)d_in[1];
    const float* W_ada = (const float*)d_in[2];
    const float* b_ada = (const float*)d_in[3];
    const float* W_qkv = (const float*)d_in[4];
    const float* b_qkv = (const float*)d_in[5];
    const float* W_out = (const float*)d_in[6];
    const float* b_out = (const float*)d_in[7];
    float* out = (float*)d_out;

    cudaFuncSetAttribute(k_attn, cudaFuncAttributeMaxDynamicSharedMemorySize, ATTN_SMEM);

    k_stats<<<512, 256>>>(x);
    k_ada<<<8, 256>>>(cond, W_ada, b_ada);
    k_ab<<<8, 512>>>();
    k_bias1<<<1536, 256>>>(W_qkv, b_qkv);

    dim3 gq(64, 24, 8);
    k_qkv<<<gq, 256>>>(x, W_qkv);

    dim3 ga(64, 8, 8);
    k_attn<<<ga, 256, ATTN_SMEM>>>();

    dim3 go(64, 8, 8);
    k_out<<<go, 256>>>(W_out, b_out, x, out);
}

// round 3
// speedup vs baseline: 1.0371x; 1.0371x over previous
#include <cuda_runtime.h>
#include <cuda_bf16.h>
#include <mma.h>

using namespace nvcuda;

// ---------------- scratch (device globals; no allocations allowed) ----------
__device__ float g_qkv[8 * 1024 * 4096];      // Q,K channel-major [n][o<1024][s]
__device__ float g_v[8 * 8 * 4096 * 64];      // V  [n][h][s][d]
__device__ float g_y[8 * 512 * 4096];         // attention out, channel-major
__device__ float2 g_part[512];                // per-block partial (sum, sumsq)
__device__ float g_ada[8 * 1024];             // scales_shifts
__device__ float g_a[8 * 512];                // (scale+1)*rstd
__device__ float g_b[8 * 512];                // shift - mean*a
__device__ float g_bias1[8 * 1536];           // folded qkv bias

#define SAMPLE_ELEMS 2097152                   // 512*64*64
#define LD 72                                  // smem leading dim (pad)
#define ATTN_SMEM ((4 * 64 * LD + 64) * 4)

#define TF32_CVT(frag) \
    _Pragma("unroll") for (int _i = 0; _i < (frag).num_elements; _i++) \
        (frag).x[_i] = wmma::__float_to_tf32((frag).x[_i]);

// ---------------- stats: per-sample sum / sumsq ------------------------------
__global__ void k_stats(const float* __restrict__ x) {
    int n = blockIdx.x >> 6;
    int ch = blockIdx.x & 63;
    const float* p = x + (size_t)n * SAMPLE_ELEMS + (size_t)ch * 32768;
    float s = 0.f, q = 0.f;
    int t = threadIdx.x;
#pragma unroll
    for (int i = 0; i < 32; i++) {
        float4 v = *(const float4*)(p + (size_t)(i * 256 + t) * 4);
        s += v.x + v.y + v.z + v.w;
        q += v.x * v.x + v.y * v.y + v.z * v.z + v.w * v.w;
    }
#pragma unroll
    for (int off = 16; off; off >>= 1) {
        s += __shfl_down_sync(0xffffffffu, s, off);
        q += __shfl_down_sync(0xffffffffu, q, off);
    }
    __shared__ float ss[8], qq[8];
    int warp = t >> 5, lane = t & 31;
    if (lane == 0) { ss[warp] = s; qq[warp] = q; }
    __syncthreads();
    if (t == 0) {
        float S = 0.f, Q = 0.f;
#pragma unroll
        for (int i = 0; i < 8; i++) { S += ss[i]; Q += qq[i]; }
        g_part[blockIdx.x] = make_float2(S, Q);
    }
}

// ---------------- adaLN: scales_shifts = cond @ W_ada + b_ada ---------------
__global__ void k_ada(const float* __restrict__ cond, const float* __restrict__ Wa,
                      const float* __restrict__ ba) {
    int n = blockIdx.x;
    __shared__ float cs[512];
    int t = threadIdx.x;
    cs[t] = cond[n * 512 + t];
    cs[t + 256] = cond[n * 512 + t + 256];
    __syncthreads();
    float acc[4] = {0.f, 0.f, 0.f, 0.f};
    for (int f = 0; f < 512; f++) {
        float cv = cs[f];
#pragma unroll
        for (int j = 0; j < 4; j++) acc[j] += cv * Wa[f * 1024 + t + j * 256];
    }
#pragma unroll
    for (int j = 0; j < 4; j++) g_ada[n * 1024 + t + j * 256] = acc[j] + ba[t + j * 256];
}

// ---------------- fold LN stats + adaLN into per-channel affine -------------
__global__ void k_ab() {
    int n = blockIdx.x;
    int t = threadIdx.x;  // 512 threads
    __shared__ float s_mean, s_rstd;
    if (t == 0) {
        float S = 0.f, Q = 0.f;
        for (int i = 0; i < 64; i++) {
            float2 p = g_part[n * 64 + i];
            S += p.x; Q += p.y;
        }
        float mean = S / (float)SAMPLE_ELEMS;
        float var = Q / (float)SAMPLE_ELEMS - mean * mean;
        s_mean = mean;
        s_rstd = rsqrtf(var + 1e-5f);
    }
    __syncthreads();
    float scale = g_ada[n * 1024 + t];
    float shift = g_ada[n * 1024 + 512 + t];
    float a = (scale + 1.f) * s_rstd;
    g_a[n * 512 + t] = a;
    g_b[n * 512 + t] = shift - s_mean * a;
}

// ---------------- folded bias: bias1[n,o] = b_qkv[o] + sum_c W[o,c]*b[n,c] --
__global__ void k_bias1(const float* __restrict__ Wqkv, const float* __restrict__ bqkv) {
    int warp = (blockIdx.x * blockDim.x + threadIdx.x) >> 5;
    int lane = threadIdx.x & 31;
    int n = warp / 1536, o = warp % 1536;
    const float* wr = Wqkv + (size_t)o * 512;
    const float* bb = g_b + n * 512;
    float acc = 0.f;
    for (int c = lane; c < 512; c += 32) acc += wr[c] * bb[c];
#pragma unroll
    for (int off = 16; off; off >>= 1) acc += __shfl_xor_sync(0xffffffffu, acc, off);
    if (lane == 0) g_bias1[warp] = bqkv[o] + acc;
}

// ---------------- QKV GEMM via wmma tf32 (norm folded into A) ---------------
__global__ __launch_bounds__(256) void k_qkv(const float* __restrict__ x,
                                             const float* __restrict__ W) {
    __shared__ float As[64 * LD];   // [o][c] row-major, also reused as Os
    __shared__ float Bs[64 * LD];   // [c][s] row-major
    int n = blockIdx.z, o0 = blockIdx.y * 64, s0 = blockIdx.x * 64;
    int tid = threadIdx.x;
    int wid = tid >> 5;
    int warp_m = wid >> 1, warp_n = wid & 1;
    const float* ap = g_a + n * 512;

    wmma::fragment<wmma::accumulator, 16, 16, 8, float> acc[2];
    wmma::fill_fragment(acc[0], 0.f);
    wmma::fill_fragment(acc[1], 0.f);

    int lr = tid >> 2, lc4 = (tid & 3) * 16;
    for (int c0 = 0; c0 < 512; c0 += 64) {
        __syncthreads();
#pragma unroll
        for (int u = 0; u < 4; u++) {
            int c = lc4 + u * 4;
            float4 wv = *(const float4*)(W + (size_t)(o0 + lr) * 512 + c0 + c);
            float4 av = *(const float4*)(ap + c0 + c);
            wv.x *= av.x; wv.y *= av.y; wv.z *= av.z; wv.w *= av.w;
            *(float4*)(As + lr * LD + c) = wv;
            float4 xv = *(const float4*)(x + (size_t)n * 512 * 4096 +
                                         (size_t)(c0 + lr) * 4096 + s0 + c);
            *(float4*)(Bs + lr * LD + c) = xv;
        }
        __syncthreads();
#pragma unroll
        for (int kk = 0; kk < 64; kk += 8) {
            wmma::fragment<wmma::matrix_a, 16, 16, 8, wmma::precision::tf32, wmma::row_major> af;
            wmma::load_matrix_sync(af, As + warp_m * 16 * LD + kk, LD);
            TF32_CVT(af);
#pragma unroll
            for (int sub = 0; sub < 2; sub++) {
                wmma::fragment<wmma::matrix_b, 16, 16, 8, wmma::precision::tf32, wmma::row_major> bf;
                wmma::load_matrix_sync(bf, Bs + kk * LD + warp_n * 32 + sub * 16, LD);
                TF32_CVT(bf);
                wmma::mma_sync(acc[sub], af, bf, acc[sub]);
            }
        }
    }
    __syncthreads();
    float* Os = As;
    wmma::store_matrix_sync(Os + warp_m * 16 * LD + warp_n * 32, acc[0], LD, wmma::mem_row_major);
    wmma::store_matrix_sync(Os + warp_m * 16 * LD + warp_n * 32 + 16, acc[1], LD, wmma::mem_row_major);
    __syncthreads();

    if (o0 < 1024) {  // Q and K: channel-major [n][o][s]
        int o = tid >> 2;
        float bb = g_bias1[n * 1536 + o0 + o];
        float* outp = g_qkv + ((size_t)n * 1024 + o0 + o) * 4096 + s0;
#pragma unroll
        for (int u = 0; u < 4; u++) {
            int s = lc4 + u * 4;
            float4 v = *(const float4*)(Os + o * LD + s);
            v.x += bb; v.y += bb; v.z += bb; v.w += bb;
            *(float4*)(outp + s) = v;
        }
    } else {          // V: transpose to [n][h][s][d]
        int h = (o0 - 1024) >> 6;
        float* vout = g_v + ((size_t)(n * 8 + h) * 4096 + s0) * 64;
        int sl = tid >> 2, d4 = (tid & 3) * 16;
        const float* bptr = g_bias1 + n * 1536 + o0;
#pragma unroll
        for (int u = 0; u < 4; u++) {
            int d = d4 + u * 4;
            float4 v = make_float4(Os[(d + 0) * LD + sl] + bptr[d + 0],
                                   Os[(d + 1) * LD + sl] + bptr[d + 1],
                                   Os[(d + 2) * LD + sl] + bptr[d + 2],
                                   Os[(d + 3) * LD + sl] + bptr[d + 3]);
            *(float4*)(vout + (size_t)sl * 64 + d) = v;
        }
    }
}

// ---------------- attention via wmma tf32 (no-max softmax) ------------------
__global__ __launch_bounds__(256) void k_attn() {
    extern __shared__ float sm[];
    float* Qs = sm;               // [d][q] ld LD  (col-major A)
    float* Ks = sm + 64 * LD;     // [d][key] ld LD (row-major B for S)
    float* Vs = sm + 2 * 64 * LD; // [t][d] ld LD  (row-major B for O)
    float* Ss = sm + 3 * 64 * LD; // [q][t] ld LD  (S then P; finally O)
    float* ls = sm + 4 * 64 * LD; // [64] row sums

    int qt = blockIdx.x, h = blockIdx.y, n = blockIdx.z;
    int tid = threadIdx.x;
    int wid = tid >> 5;
    int warp_m = wid >> 1, warp_n = wid & 1;

    const float* qb = g_qkv + ((size_t)(n * 1024) + h * 64) * 4096 + qt * 64;
    const float* kb = g_qkv + ((size_t)(n * 1024) + 512 + h * 64) * 4096;
    const float* vb = g_v + (size_t)(n * 8 + h) * 4096 * 64;

    int lr = tid >> 2, lc4 = (tid & 3) * 16;
    // load Q tile [d][q], pre-scaled by 1/8 (dh^-0.5 total on the product)
#pragma unroll
    for (int u = 0; u < 4; u++) {
        int q = lc4 + u * 4;
        float4 v = *(const float4*)(qb + (size_t)lr * 4096 + q);
        v.x *= 0.125f; v.y *= 0.125f; v.z *= 0.125f; v.w *= 0.125f;
        *(float4*)(Qs + lr * LD + q) = v;
    }
    if (tid < 64) ls[tid] = 0.f;

    wmma::fragment<wmma::accumulator, 16, 16, 8, float> o_acc[2];
    wmma::fill_fragment(o_acc[0], 0.f);
    wmma::fill_fragment(o_acc[1], 0.f);

    for (int jt = 0; jt < 64; jt++) {
        __syncthreads();
        // load K tile [d][key] and V tile [t][d]
#pragma unroll
        for (int u = 0; u < 4; u++) {
            int c = lc4 + u * 4;
            float4 kv = *(const float4*)(kb + (size_t)lr * 4096 + jt * 64 + c);
            *(float4*)(Ks + lr * LD + c) = kv;
            float4 vv = *(const float4*)(vb + (size_t)(jt * 64 + lr) * 64 + c);
            *(float4*)(Vs + lr * LD + c) = vv;
        }
        __syncthreads();

        // S = Q^T K  (A col-major from Qs, B row-major from Ks)
        wmma::fragment<wmma::accumulator, 16, 16, 8, float> s_acc[2];
        wmma::fill_fragment(s_acc[0], 0.f);
        wmma::fill_fragment(s_acc[1], 0.f);
#pragma unroll
        for (int kk = 0; kk < 64; kk += 8) {
            wmma::fragment<wmma::matrix_a, 16, 16, 8, wmma::precision::tf32, wmma::col_major> af;
            wmma::load_matrix_sync(af, Qs + kk * LD + warp_m * 16, LD);
            TF32_CVT(af);
#pragma unroll
            for (int sub = 0; sub < 2; sub++) {
                wmma::fragment<wmma::matrix_b, 16, 16, 8, wmma::precision::tf32, wmma::row_major> bf;
                wmma::load_matrix_sync(bf, Ks + kk * LD + warp_n * 32 + sub * 16, LD);
                TF32_CVT(bf);
                wmma::mma_sync(s_acc[sub], af, bf, s_acc[sub]);
            }
        }
        wmma::store_matrix_sync(Ss + warp_m * 16 * LD + warp_n * 32, s_acc[0], LD, wmma::mem_row_major);
        wmma::store_matrix_sync(Ss + warp_m * 16 * LD + warp_n * 32 + 16, s_acc[1], LD, wmma::mem_row_major);
        __syncthreads();

        // P = exp(S) in-place; accumulate row sums (no max subtraction: |S| <~ 14)
        {
            float psum = 0.f;
            float* row = Ss + lr * LD + lc4;
#pragma unroll
            for (int u = 0; u < 4; u++) {
                float4 v = *(float4*)(row + u * 4);
                v.x = __expf(v.x); v.y = __expf(v.y);
                v.z = __expf(v.z); v.w = __expf(v.w);
                psum += v.x + v.y + v.z + v.w;
                *(float4*)(row + u * 4) = v;
            }
            psum += __shfl_down_sync(0xffffffffu, psum, 1, 4);
            psum += __shfl_down_sync(0xffffffffu, psum, 2, 4);
            if ((tid & 3) == 0) ls[lr] += psum;
        }
        __syncthreads();

        // O += P * V  (A row-major from Ss, B row-major from Vs)
#pragma unroll
        for (int kk = 0; kk < 64; kk += 8) {
            wmma::fragment<wmma::matrix_a, 16, 16, 8, wmma::precision::tf32, wmma::row_major> af;
            wmma::load_matrix_sync(af, Ss + warp_m * 16 * LD + kk, LD);
            TF32_CVT(af);
#pragma unroll
            for (int sub = 0; sub < 2; sub++) {
                wmma::fragment<wmma::matrix_b, 16, 16, 8, wmma::precision::tf32, wmma::row_major> bf;
                wmma::load_matrix_sync(bf, Vs + kk * LD + warp_n * 32 + sub * 16, LD);
                TF32_CVT(bf);
                wmma::mma_sync(o_acc[sub], af, bf, o_acc[sub]);
            }
        }
    }

    __syncthreads();
    wmma::store_matrix_sync(Ss + warp_m * 16 * LD + warp_n * 32, o_acc[0], LD, wmma::mem_row_major);
    wmma::store_matrix_sync(Ss + warp_m * 16 * LD + warp_n * 32 + 16, o_acc[1], LD, wmma::mem_row_major);
    __syncthreads();

    // normalize by row sum, write y channel-major [n][h*64+d][s]
    float* yb = g_y + ((size_t)(n * 512) + h * 64) * 4096 + qt * 64;
    int d = tid >> 2;
#pragma unroll
    for (int u = 0; u < 4; u++) {
        int q = lc4 + u * 4;
        float4 o = make_float4(Ss[(q + 0) * LD + d] / ls[q + 0],
                               Ss[(q + 1) * LD + d] / ls[q + 1],
                               Ss[(q + 2) * LD + d] / ls[q + 2],
                               Ss[(q + 3) * LD + d] / ls[q + 3]);
        *(float4*)(yb + (size_t)d * 4096 + q) = o;
    }
}

// ---------------- output projection + bias + residual (wmma tf32) -----------
__global__ __launch_bounds__(256) void k_out(const float* __restrict__ W,
                                             const float* __restrict__ bo,
                                             const float* __restrict__ x,
                                             float* __restrict__ out) {
    __shared__ float As[64 * LD];
    __shared__ float Bs[64 * LD];
    int n = blockIdx.z, o0 = blockIdx.y * 64, s0 = blockIdx.x * 64;
    int tid = threadIdx.x;
    int wid = tid >> 5;
    int warp_m = wid >> 1, warp_n = wid & 1;

    wmma::fragment<wmma::accumulator, 16, 16, 8, float> acc[2];
    wmma::fill_fragment(acc[0], 0.f);
    wmma::fill_fragment(acc[1], 0.f);

    int lr = tid >> 2, lc4 = (tid & 3) * 16;
    for (int c0 = 0; c0 < 512; c0 += 64) {
        __syncthreads();
#pragma unroll
        for (int u = 0; u < 4; u++) {
            int c = lc4 + u * 4;
            float4 wv = *(const float4*)(W + (size_t)(o0 + lr) * 512 + c0 + c);
            *(float4*)(As + lr * LD + c) = wv;
            float4 yv = *(const float4*)(g_y + (size_t)n * 512 * 4096 +
                                         (size_t)(c0 + lr) * 4096 + s0 + c);
            *(float4*)(Bs + lr * LD + c) = yv;
        }
        __syncthreads();
#pragma unroll
        for (int kk = 0; kk < 64; kk += 8) {
            wmma::fragment<wmma::matrix_a, 16, 16, 8, wmma::precision::tf32, wmma::row_major> af;
            wmma::load_matrix_sync(af, As + warp_m * 16 * LD + kk, LD);
            TF32_CVT(af);
#pragma unroll
            for (int sub = 0; sub < 2; sub++) {
                wmma::fragment<wmma::matrix_b, 16, 16, 8, wmma::precision::tf32, wmma::row_major> bf;
                wmma::load_matrix_sync(bf, Bs + kk * LD + warp_n * 32 + sub * 16, LD);
                TF32_CVT(bf);
                wmma::mma_sync(acc[sub], af, bf, acc[sub]);
            }
        }
    }
    __syncthreads();
    float* Os = As;
    wmma::store_matrix_sync(Os + warp_m * 16 * LD + warp_n * 32, acc[0], LD, wmma::mem_row_major);
    wmma::store_matrix_sync(Os + warp_m * 16 * LD + warp_n * 32 + 16, acc[1], LD, wmma::mem_row_major);
    __syncthreads();

    int o = tid >> 2;
    float bb = bo[o0 + o];
    size_t base = ((size_t)n * 512 + o0 + o) * 4096 + s0;
#pragma unroll
    for (int u = 0; u < 4; u++) {
        int s = lc4 + u * 4;
        float4 v = *(const float4*)(Os + o * LD + s);
        float4 xr = *(const float4*)(x + base + s);
        v.x += bb + xr.x; v.y += bb + xr.y; v.z += bb + xr.z; v.w += bb + xr.w;
        *(float4*)(out + base + s) = v;
    }
}

// ---------------- launch -----------------------------------------------------
extern "C" void kernel_launch(void* const* d_in, const int* in_sizes, int n_in,
                              void* d_out, int out_size) {
    const float* x     = (const float*)d_in[0];
    const float* cond  = (const float*)d_in[1];
    const float* W_ada = (const float*)d_in[2];
    const float* b_ada = (const float*)d_in[3];
    const float* W_qkv = (const float*)d_in[4];
    const float* b_qkv = (const float*)d_in[5];
    const float* W_out = (const float*)d_in[6];
    const float* b_out = (const float*)d_in[7];
    float* out = (float*)d_out;

    cudaFuncSetAttribute(k_attn, cudaFuncAttributeMaxDynamicSharedMemorySize, ATTN_SMEM);

    k_stats<<<512, 256>>>(x);
    k_ada<<<8, 256>>>(cond, W_ada, b_ada);
    k_ab<<<8, 512>>>();
    k_bias1<<<1536, 256>>>(W_qkv, b_qkv);

    dim3 gq(64, 24, 8);
    k_qkv<<<gq, 256>>>(x, W_qkv);

    dim3 ga(64, 8, 8);
    k_attn<<<ga, 256, ATTN_SMEM>>>();

    dim3 go(64, 8, 8);
    k_out<<<go, 256>>>(W_out, b_out, x, out);
}

// round 5
// speedup vs baseline: 3.2655x; 3.1486x over previous
#include <cuda_runtime.h>
#include <cuda_bf16.h>
#include <cuda_fp16.h>
#include <mma.h>
#include <cstdint>

using namespace nvcuda;

// ---------------- scratch (device globals; no allocations allowed) ----------
__device__ __half g_qh[8 * 8 * 4096 * 64];    // Q fp16 [n][h][s][d] (prescaled by 1/8*log2e)
__device__ __half g_kh[8 * 8 * 4096 * 64];    // K fp16 [n][h][s][d]
__device__ __half g_vh[8 * 8 * 4096 * 64];    // V fp16 [n][h][s][d]
__device__ float g_y[8 * 512 * 4096];         // attention out, channel-major
__device__ float2 g_part[512];
__device__ float g_ada[8 * 1024];
__device__ float g_a[8 * 512];
__device__ float g_b[8 * 512];
__device__ float g_bias1[8 * 1536];

#define SAMPLE_ELEMS 2097152
#define LDO 72                 // fp32 smem leading dim (k_out)
#define LDH 72                 // fp16 smem leading dim
#define QSCALE 0.18033688f     // 0.125 * log2(e)
#define PBIAS 15.0f            // p = 2^(S - 15)

#define TF32_CVT(frag) \
    _Pragma("unroll") for (int _i = 0; _i < (frag).num_elements; _i++) \
        (frag).x[_i] = wmma::__float_to_tf32((frag).x[_i]);

__device__ __forceinline__ float ex2f(float x) {
    float r; asm("ex2.approx.f32 %0, %1;" : "=f"(r) : "f"(x)); return r;
}

// ---------------- stats: per-sample sum / sumsq ------------------------------
__global__ void k_stats(const float* __restrict__ x) {
    int n = blockIdx.x >> 6;
    int ch = blockIdx.x & 63;
    const float* p = x + (size_t)n * SAMPLE_ELEMS + (size_t)ch * 32768;
    float s = 0.f, q = 0.f;
    int t = threadIdx.x;
#pragma unroll
    for (int i = 0; i < 32; i++) {
        float4 v = *(const float4*)(p + (size_t)(i * 256 + t) * 4);
        s += v.x + v.y + v.z + v.w;
        q += v.x * v.x + v.y * v.y + v.z * v.z + v.w * v.w;
    }
#pragma unroll
    for (int off = 16; off; off >>= 1) {
        s += __shfl_down_sync(0xffffffffu, s, off);
        q += __shfl_down_sync(0xffffffffu, q, off);
    }
    __shared__ float ss[8], qq[8];
    int warp = t >> 5, lane = t & 31;
    if (lane == 0) { ss[warp] = s; qq[warp] = q; }
    __syncthreads();
    if (t == 0) {
        float S = 0.f, Q = 0.f;
#pragma unroll
        for (int i = 0; i < 8; i++) { S += ss[i]; Q += qq[i]; }
        g_part[blockIdx.x] = make_float2(S, Q);
    }
}

// ---------------- adaLN -----------------------------------------------------
__global__ void k_ada(const float* __restrict__ cond, const float* __restrict__ Wa,
                      const float* __restrict__ ba) {
    int n = blockIdx.x;
    __shared__ float cs[512];
    int t = threadIdx.x;
    cs[t] = cond[n * 512 + t];
    cs[t + 256] = cond[n * 512 + t + 256];
    __syncthreads();
    float acc[4] = {0.f, 0.f, 0.f, 0.f};
    for (int f = 0; f < 512; f++) {
        float cv = cs[f];
#pragma unroll
        for (int j = 0; j < 4; j++) acc[j] += cv * Wa[f * 1024 + t + j * 256];
    }
#pragma unroll
    for (int j = 0; j < 4; j++) g_ada[n * 1024 + t + j * 256] = acc[j] + ba[t + j * 256];
}

// ---------------- fold LN stats + adaLN -------------------------------------
__global__ void k_ab() {
    int n = blockIdx.x;
    int t = threadIdx.x;
    __shared__ float s_mean, s_rstd;
    if (t == 0) {
        float S = 0.f, Q = 0.f;
        for (int i = 0; i < 64; i++) {
            float2 p = g_part[n * 64 + i];
            S += p.x; Q += p.y;
        }
        float mean = S / (float)SAMPLE_ELEMS;
        float var = Q / (float)SAMPLE_ELEMS - mean * mean;
        s_mean = mean;
        s_rstd = rsqrtf(var + 1e-5f);
    }
    __syncthreads();
    float scale = g_ada[n * 1024 + t];
    float shift = g_ada[n * 1024 + 512 + t];
    float a = (scale + 1.f) * s_rstd;
    g_a[n * 512 + t] = a;
    g_b[n * 512 + t] = shift - s_mean * a;
}

// ---------------- folded qkv bias -------------------------------------------
__global__ void k_bias1(const float* __restrict__ Wqkv, const float* __restrict__ bqkv) {
    int warp = (blockIdx.x * blockDim.x + threadIdx.x) >> 5;
    int lane = threadIdx.x & 31;
    int n = warp / 1536, o = warp % 1536;
    const float* wr = Wqkv + (size_t)o * 512;
    const float* bb = g_b + n * 512;
    float acc = 0.f;
    for (int c = lane; c < 512; c += 32) acc += wr[c] * bb[c];
#pragma unroll
    for (int off = 16; off; off >>= 1) acc += __shfl_xor_sync(0xffffffffu, acc, off);
    if (lane == 0) g_bias1[warp] = bqkv[o] + acc;
}

// ---------------- QKV GEMM fp16 wmma (norm folded into A) -------------------
__global__ __launch_bounds__(256) void k_qkv(const float* __restrict__ x,
                                             const float* __restrict__ W) {
    __shared__ __align__(16) char qsm[18432];
    __half* As = (__half*)qsm;             // [64][LDH]
    __half* Bs = (__half*)(qsm + 9216);    // [64][LDH]
    float* Os = (float*)qsm;               // [64][LDO] (epilogue reuse)

    int n = blockIdx.z, o0 = blockIdx.y * 64, s0 = blockIdx.x * 64;
    int tid = threadIdx.x, wid = tid >> 5;
    int wm = wid >> 1, wn = wid & 1;
    const float* ap = g_a + n * 512;

    wmma::fragment<wmma::accumulator, 16, 16, 16, float> acc[2];
    wmma::fill_fragment(acc[0], 0.f);
    wmma::fill_fragment(acc[1], 0.f);

    int lr = tid >> 2, lc4 = (tid & 3) * 16;
    for (int c0 = 0; c0 < 512; c0 += 64) {
        __syncthreads();
#pragma unroll
        for (int u = 0; u < 4; u++) {
            int c = lc4 + u * 4;
            float4 wv = *(const float4*)(W + (size_t)(o0 + lr) * 512 + c0 + c);
            float4 av = *(const float4*)(ap + c0 + c);
            *(__half2*)(As + lr * LDH + c) = __floats2half2_rn(wv.x * av.x, wv.y * av.y);
            *(__half2*)(As + lr * LDH + c + 2) = __floats2half2_rn(wv.z * av.z, wv.w * av.w);
            float4 xv = *(const float4*)(x + (size_t)n * 512 * 4096 +
                                         (size_t)(c0 + lr) * 4096 + s0 + c);
            *(__half2*)(Bs + lr * LDH + c) = __floats2half2_rn(xv.x, xv.y);
            *(__half2*)(Bs + lr * LDH + c + 2) = __floats2half2_rn(xv.z, xv.w);
        }
        __syncthreads();
#pragma unroll
        for (int k = 0; k < 4; k++) {
            wmma::fragment<wmma::matrix_a, 16, 16, 16, __half, wmma::row_major> af;
            wmma::load_matrix_sync(af, As + (wm * 16) * LDH + k * 16, LDH);
#pragma unroll
            for (int j = 0; j < 2; j++) {
                wmma::fragment<wmma::matrix_b, 16, 16, 16, __half, wmma::row_major> bf;
                wmma::load_matrix_sync(bf, Bs + (k * 16) * LDH + wn * 32 + j * 16, LDH);
                wmma::mma_sync(acc[j], af, bf, acc[j]);
            }
        }
    }
    __syncthreads();
    wmma::store_matrix_sync(Os + (wm * 16) * LDO + wn * 32, acc[0], LDO, wmma::mem_row_major);
    wmma::store_matrix_sync(Os + (wm * 16) * LDO + wn * 32 + 16, acc[1], LDO, wmma::mem_row_major);
    __syncthreads();

    const float* bptr = g_bias1 + n * 1536 + o0;
    __half* dst;
    float qs = 1.f;
    int hh;
    if (o0 < 512)       { hh = o0 >> 6;          dst = g_qh; qs = QSCALE; }
    else if (o0 < 1024) { hh = (o0 - 512) >> 6;  dst = g_kh; }
    else                { hh = (o0 - 1024) >> 6; dst = g_vh; }

    int s = tid >> 2, dg = (tid & 3) * 16;
    __half* op = dst + ((size_t)(n * 8 + hh) * 4096 + s0 + s) * 64;
#pragma unroll
    for (int u = 0; u < 8; u++) {
        int d = dg + u * 2;
        float v0 = (Os[d * LDO + s] + bptr[d]) * qs;
        float v1 = (Os[(d + 1) * LDO + s] + bptr[d + 1]) * qs;
        *(__half2*)(op + d) = __floats2half2_rn(v0, v1);
    }
}

// ---------------- attention: fp16 wmma, register softmax --------------------
// smem: Qs[128][LDH] h, Ks[2][64][LDH] h, Vs[2][64][LDH] h, Ps[128][LDH] h,
//       ls2[2][128] f.  Os (epilogue) reuses Ks+Vs (128*LDO fp32).
#define A_QS 0
#define A_KS 18432
#define A_VS 36864
#define A_PS 55296
#define A_LS 73728
#define ATTN_SMEM (A_LS + 1024)

__global__ __launch_bounds__(256, 2) void k_attn() {
    extern __shared__ __align__(16) char smraw[];
    __half* Qs = (__half*)(smraw + A_QS);
    __half* Ks = (__half*)(smraw + A_KS);
    __half* Vs = (__half*)(smraw + A_VS);
    __half* Ps = (__half*)(smraw + A_PS);
    float* ls2 = (float*)(smraw + A_LS);
    float* Os = (float*)(smraw + A_KS);   // epilogue reuse (128*LDO floats)

    int qt = blockIdx.x, h = blockIdx.y, n = blockIdx.z;
    int nh = n * 8 + h;
    int tid = threadIdx.x, wid = tid >> 5, lane = tid & 31;
    int wm = wid >> 1, wn = wid & 1;
    int g = lane >> 2, t4 = lane & 3;

    const uint4* qsrc = (const uint4*)(g_qh + ((size_t)nh * 4096 + (size_t)qt * 128) * 64);
    const uint4* ksrc = (const uint4*)(g_kh + (size_t)nh * 4096 * 64);
    const uint4* vsrc = (const uint4*)(g_vh + (size_t)nh * 4096 * 64);

    // load Q tile: 128 rows x 64 halves
    for (int i = tid; i < 1024; i += 256) {
        int row = i >> 3, c = i & 7;
        *(uint4*)(Qs + row * LDH + c * 8) = qsrc[i];
    }
    ls2[tid] = 0.f;  // 256 floats
    // preload K/V tile 0 into buffer 0
    for (int i = tid; i < 1024; i += 256) {
        int row = (i >> 3) & 63, c = i & 7;
        if (i < 512) *(uint4*)(Ks + row * LDH + c * 8) = ksrc[i];
        else         *(uint4*)(Vs + row * LDH + c * 8) = vsrc[i - 512];
    }
    __syncthreads();

    wmma::fragment<wmma::accumulator, 16, 16, 16, float> o_acc[2][2];
#pragma unroll
    for (int i = 0; i < 2; i++)
#pragma unroll
        for (int j = 0; j < 2; j++) wmma::fill_fragment(o_acc[i][j], 0.f);

    float* lsw = ls2 + wn * 128;

    for (int jt = 0; jt < 64; jt++) {
        int cur = jt & 1, nxt = cur ^ 1;
        // prefetch next K/V tile (overlaps S GEMM; consumed after next sync pair)
        if (jt < 63) {
            const uint4* kp = ksrc + (size_t)(jt + 1) * 512;
            const uint4* vp = vsrc + (size_t)(jt + 1) * 512;
            for (int i = tid; i < 1024; i += 256) {
                int row = (i >> 3) & 63, c = i & 7;
                if (i < 512) *(uint4*)(Ks + nxt * 64 * LDH + row * LDH + c * 8) = kp[i];
                else         *(uint4*)(Vs + nxt * 64 * LDH + row * LDH + c * 8) = vp[i - 512];
            }
        }
        // S = Q * K^T  (128x64, k=64)
        wmma::fragment<wmma::accumulator, 16, 16, 16, float> s_acc[2][2];
#pragma unroll
        for (int i = 0; i < 2; i++)
#pragma unroll
            for (int j = 0; j < 2; j++) wmma::fill_fragment(s_acc[i][j], 0.f);
#pragma unroll
        for (int k = 0; k < 4; k++) {
            wmma::fragment<wmma::matrix_a, 16, 16, 16, __half, wmma::row_major> af[2];
            wmma::load_matrix_sync(af[0], Qs + (wm * 32) * LDH + k * 16, LDH);
            wmma::load_matrix_sync(af[1], Qs + (wm * 32 + 16) * LDH + k * 16, LDH);
#pragma unroll
            for (int j = 0; j < 2; j++) {
                wmma::fragment<wmma::matrix_b, 16, 16, 16, __half, wmma::col_major> bf;
                wmma::load_matrix_sync(bf, Ks + cur * 64 * LDH + (wn * 32 + j * 16) * LDH + k * 16, LDH);
                wmma::mma_sync(s_acc[0][j], af[0], bf, s_acc[0][j]);
                wmma::mma_sync(s_acc[1][j], af[1], bf, s_acc[1][j]);
            }
        }
        // register softmax: p = 2^(S-15); fragment layout (sm_80+ mma.16816):
        // x[0],x[1]=(row g,   col 2t,2t+1)   x[4],x[5]=(row g,   col 2t+8,2t+9)
        // x[2],x[3]=(row g+8, col 2t,2t+1)   x[6],x[7]=(row g+8, col 2t+8,2t+9)
#pragma unroll
        for (int i = 0; i < 2; i++) {
            int r1 = wm * 32 + i * 16 + g;
            float s1 = 0.f, s2 = 0.f;
#pragma unroll
            for (int j = 0; j < 2; j++) {
                float p0 = ex2f(s_acc[i][j].x[0] - PBIAS);
                float p1 = ex2f(s_acc[i][j].x[1] - PBIAS);
                float p2 = ex2f(s_acc[i][j].x[2] - PBIAS);
                float p3 = ex2f(s_acc[i][j].x[3] - PBIAS);
                float p4 = ex2f(s_acc[i][j].x[4] - PBIAS);
                float p5 = ex2f(s_acc[i][j].x[5] - PBIAS);
                float p6 = ex2f(s_acc[i][j].x[6] - PBIAS);
                float p7 = ex2f(s_acc[i][j].x[7] - PBIAS);
                s1 += p0 + p1 + p4 + p5;
                s2 += p2 + p3 + p6 + p7;
                int cb = wn * 32 + j * 16 + 2 * t4;
                __half* pr1 = Ps + r1 * LDH + cb;
                __half* pr2 = pr1 + 8 * LDH;
                *(__half2*)pr1 = __floats2half2_rn(p0, p1);
                *(__half2*)(pr1 + 8) = __floats2half2_rn(p4, p5);
                *(__half2*)pr2 = __floats2half2_rn(p2, p3);
                *(__half2*)(pr2 + 8) = __floats2half2_rn(p6, p7);
            }
            s1 += __shfl_xor_sync(0xffffffffu, s1, 1);
            s1 += __shfl_xor_sync(0xffffffffu, s1, 2);
            s2 += __shfl_xor_sync(0xffffffffu, s2, 1);
            s2 += __shfl_xor_sync(0xffffffffu, s2, 2);
            if (t4 == 0) { lsw[r1] += s1; lsw[r1 + 8] += s2; }
        }
        __syncthreads();
        // O += P * V  (128x64, k=64)
#pragma unroll
        for (int k = 0; k < 4; k++) {
            wmma::fragment<wmma::matrix_a, 16, 16, 16, __half, wmma::row_major> af[2];
            wmma::load_matrix_sync(af[0], Ps + (wm * 32) * LDH + k * 16, LDH);
            wmma::load_matrix_sync(af[1], Ps + (wm * 32 + 16) * LDH + k * 16, LDH);
#pragma unroll
            for (int j = 0; j < 2; j++) {
                wmma::fragment<wmma::matrix_b, 16, 16, 16, __half, wmma::row_major> bf;
                wmma::load_matrix_sync(bf, Vs + cur * 64 * LDH + (k * 16) * LDH + wn * 32 + j * 16, LDH);
                wmma::mma_sync(o_acc[0][j], af[0], bf, o_acc[0][j]);
                wmma::mma_sync(o_acc[1][j], af[1], bf, o_acc[1][j]);
            }
        }
        __syncthreads();
    }

    // epilogue: stage O to smem (reuse K/V region), normalize, write y
#pragma unroll
    for (int i = 0; i < 2; i++)
#pragma unroll
        for (int j = 0; j < 2; j++)
            wmma::store_matrix_sync(Os + (wm * 32 + i * 16) * LDO + wn * 32 + j * 16,
                                    o_acc[i][j], LDO, wmma::mem_row_major);
    if (tid < 128) ls2[tid] = 1.f / (ls2[tid] + ls2[128 + tid]);
    __syncthreads();
    float* yb = g_y + ((size_t)n * 512 + h * 64) * 4096 + (size_t)qt * 128;
    for (int i = tid; i < 8192; i += 256) {
        int q = i & 127, d = i >> 7;
        yb[(size_t)d * 4096 + q] = Os[q * LDO + d] * ls2[q];
    }
}

// ---------------- output projection + bias + residual (wmma tf32) -----------
__global__ __launch_bounds__(256) void k_out(const float* __restrict__ W,
                                             const float* __restrict__ bo,
                                             const float* __restrict__ x,
                                             float* __restrict__ out) {
    __shared__ float As[64 * LDO];
    __shared__ float Bs[64 * LDO];
    int n = blockIdx.z, o0 = blockIdx.y * 64, s0 = blockIdx.x * 64;
    int tid = threadIdx.x;
    int wid = tid >> 5;
    int warp_m = wid >> 1, warp_n = wid & 1;

    wmma::fragment<wmma::accumulator, 16, 16, 8, float> acc[2];
    wmma::fill_fragment(acc[0], 0.f);
    wmma::fill_fragment(acc[1], 0.f);

    int lr = tid >> 2, lc4 = (tid & 3) * 16;
    for (int c0 = 0; c0 < 512; c0 += 64) {
        __syncthreads();
#pragma unroll
        for (int u = 0; u < 4; u++) {
            int c = lc4 + u * 4;
            float4 wv = *(const float4*)(W + (size_t)(o0 + lr) * 512 + c0 + c);
            *(float4*)(As + lr * LDO + c) = wv;
            float4 yv = *(const float4*)(g_y + (size_t)n * 512 * 4096 +
                                         (size_t)(c0 + lr) * 4096 + s0 + c);
            *(float4*)(Bs + lr * LDO + c) = yv;
        }
        __syncthreads();
#pragma unroll
        for (int kk = 0; kk < 64; kk += 8) {
            wmma::fragment<wmma::matrix_a, 16, 16, 8, wmma::precision::tf32, wmma::row_major> af;
            wmma::load_matrix_sync(af, As + warp_m * 16 * LDO + kk, LDO);
            TF32_CVT(af);
#pragma unroll
            for (int sub = 0; sub < 2; sub++) {
                wmma::fragment<wmma::matrix_b, 16, 16, 8, wmma::precision::tf32, wmma::row_major> bf;
                wmma::load_matrix_sync(bf, Bs + kk * LDO + warp_n * 32 + sub * 16, LDO);
                TF32_CVT(bf);
                wmma::mma_sync(acc[sub], af, bf, acc[sub]);
            }
        }
    }
    __syncthreads();
    float* Os = As;
    wmma::store_matrix_sync(Os + warp_m * 16 * LDO + warp_n * 32, acc[0], LDO, wmma::mem_row_major);
    wmma::store_matrix_sync(Os + warp_m * 16 * LDO + warp_n * 32 + 16, acc[1], LDO, wmma::mem_row_major);
    __syncthreads();

    int o = tid >> 2;
    float bb = bo[o0 + o];
    size_t base = ((size_t)n * 512 + o0 + o) * 4096 + s0;
#pragma unroll
    for (int u = 0; u < 4; u++) {
        int s = lc4 + u * 4;
        float4 v = *(const float4*)(Os + o * LDO + s);
        float4 xr = *(const float4*)(x + base + s);
        v.x += bb + xr.x; v.y += bb + xr.y; v.z += bb + xr.z; v.w += bb + xr.w;
        *(float4*)(out + base + s) = v;
    }
}

// ---------------- launch -----------------------------------------------------
extern "C" void kernel_launch(void* const* d_in, const int* in_sizes, int n_in,
                              void* d_out, int out_size) {
    const float* x     = (const float*)d_in[0];
    const float* cond  = (const float*)d_in[1];
    const float* W_ada = (const float*)d_in[2];
    const float* b_ada = (const float*)d_in[3];
    const float* W_qkv = (const float*)d_in[4];
    const float* b_qkv = (const float*)d_in[5];
    const float* W_out = (const float*)d_in[6];
    const float* b_out = (const float*)d_in[7];
    float* out = (float*)d_out;

    cudaFuncSetAttribute(k_attn, cudaFuncAttributeMaxDynamicSharedMemorySize, ATTN_SMEM);

    k_stats<<<512, 256>>>(x);
    k_ada<<<8, 256>>>(cond, W_ada, b_ada);
    k_ab<<<8, 512>>>();
    k_bias1<<<1536, 256>>>(W_qkv, b_qkv);

    dim3 gq(64, 24, 8);
    k_qkv<<<gq, 256>>>(x, W_qkv);

    dim3 ga(32, 8, 8);
    k_attn<<<ga, 256, ATTN_SMEM>>>();

    dim3 go(64, 8, 8);
    k_out<<<go, 256>>>(W_out, b_out, x, out);
}